// round 7
// baseline (speedup 1.0000x reference)
#include <cuda_runtime.h>
#include <cuda_bf16.h>

// GCNet cost-volume + softargmax, specialized:
//   B=1, C=32, H=128, W=256, dmin=min_disp/2, dmax=max_disp/2 (default 0,64)
//
//   channels [0,C):   softmax over d-constant vector -> uniform -> mean disparity
//   channels [C,2C):  sliding-window softargmax over feaR.
//
// R1: fp64 -> fp32: 105 -> 10.7us (FP64-pipe-bound).
// R4: warp-per-row + smem windows: 10.7 -> 8.9us.
// R5: shfl windows (dmin=0,D=64 fast path) + grid rebalance: 8.9 -> 6.6us.
// R6: windows need only DIFFERENCES, not absolute prefixes:
//       dP(w) = slide8(tot)[lane-1] + eincl[i] - eincl_i(lane-8)
//     - 5-step full warp scan -> 3-step sliding-8 sum (+1 shift)
//     - no exclusive-scan fixup, no 16 base-add FADDs
//     - partial-window corr in 3 fp ops (fminf), clamped predication unifies
//       lanes 0-7 (window 0..w) with lanes 8-31 (full 64-window).

#define GC_C 32
#define GC_H 128
#define GC_W 256
#define RPB  4                  // rows per block (4 warps, one per SMSP)
#define SPAD 292                // generic-fallback padded row

__device__ __forceinline__ int pad_idx(int i) { return i + (i >> 3); }

__global__ __launch_bounds__(32 * RPB)
void gcnet_softargmax_kernel(const float* __restrict__ feaR,
                             const int* __restrict__ p_min_disp,
                             const int* __restrict__ p_max_disp,
                             float* __restrict__ out)
{
    __shared__ float sP[RPB][SPAD];   // generic fallback only
    __shared__ float sQ[RPB][SPAD];

    const int lane  = threadIdx.x & 31;
    const int wrp   = threadIdx.x >> 5;
    const int row   = blockIdx.x * RPB + wrp;      // row = c*H + h, 0..4095
    const int wbase = lane * 8;

    // ---- start the loads immediately
    const float* rptr = feaR + (size_t)row * GC_W + wbase;
    const float4 v0 = *(const float4*)(rptr);
    const float4 v1 = *(const float4*)(rptr + 4);

    const int min_disp = p_min_disp ? *p_min_disp : 0;
    const int max_disp = p_max_disp ? *p_max_disp : 128;
    const int dmin = min_disp / 2;
    const int dmax = max_disp / 2;
    const int D    = dmax - dmin;
    const float meanD    = 0.5f * (float)(dmin + dmax - 1);
    const float sumAll_d = meanD * (float)D;

    // ---- left channels: constant; fire these stores before compute
    float* outL = out + (size_t)row * GC_W + wbase;
    const float4 cst = make_float4(meanD, meanD, meanD, meanD);
    *(float4*)(outL)     = cst;
    *(float4*)(outL + 4) = cst;

    // ---- exp + weighted values
    const float xs[8] = { v0.x, v0.y, v0.z, v0.w, v1.x, v1.y, v1.z, v1.w };
    const float fw = (float)wbase;
    float e[8], q[8];
    #pragma unroll
    for (int i = 0; i < 8; i++) {
        e[i] = __expf(xs[i]);
        q[i] = (fw + (float)i) * e[i];
    }

    // ---- in-lane serial inclusive scan (local, no base)
    #pragma unroll
    for (int i = 1; i < 8; i++) { e[i] += e[i - 1]; q[i] += q[i - 1]; }

    const float tot_e = e[7], tot_q = q[7];
    float res[8];

    if (dmin == 0 && D == 64) {
        // ===== fast path: only window differences needed.
        // slide-8 clamped sums of lane totals: ae = sum tot[lane-7..lane]
        float ae = tot_e, aq = tot_q;
        #pragma unroll
        for (int off = 1; off <= 4; off <<= 1) {
            const float te = __shfl_up_sync(0xffffffffu, ae, off);
            const float tq = __shfl_up_sync(0xffffffffu, aq, off);
            if (lane >= off) { ae += te; aq += tq; }
        }
        // bdiff = sum tot[lane-8..lane-1] (clamped; ==exclusive prefix for lane<8)
        const float bdeu = __shfl_up_sync(0xffffffffu, ae, 1);
        const float bdqu = __shfl_up_sync(0xffffffffu, aq, 1);
        const float bde = (lane >= 1) ? bdeu : 0.0f;
        const float bdq = (lane >= 1) ? bdqu : 0.0f;

        #pragma unroll
        for (int i = 0; i < 8; i++) {
            const float fwi = fw + (float)i;
            const float pbu = __shfl_up_sync(0xffffffffu, e[i], 8);
            const float qbu = __shfl_up_sync(0xffffffffu, q[i], 8);
            const float pb  = (lane >= 8) ? pbu : 0.0f;
            const float qb  = (lane >= 8) ? qbu : 0.0f;
            const float dP = bde + e[i] - pb;
            const float dQ = bdq + q[i] - qb;
            // partial-window corrections; zero for w >= 63 (all lanes >= 8)
            const float fm   = fminf(63.0f, fwi);           // highest valid disparity
            const float fInv = 63.0f - fm;                  // invalid count (exp(0)=1)
            const float corr = 2016.0f - 0.5f * fm * (fm + 1.0f);
            const float s0 = dP + fInv;
            const float s1 = fwi * dP - dQ + corr;
            res[i] = __fdividef(s1, s0);
        }
    } else {
        // ===== generic fallback (arbitrary dmin/dmax): absolute prefixes + smem
        float se = tot_e, sq = tot_q;
        #pragma unroll
        for (int off = 1; off < 32; off <<= 1) {
            const float te = __shfl_up_sync(0xffffffffu, se, off);
            const float tq = __shfl_up_sync(0xffffffffu, sq, off);
            if (lane >= off) { se += te; sq += tq; }
        }
        const float base_e = se - tot_e;
        const float base_q = sq - tot_q;
        #pragma unroll
        for (int i = 0; i < 8; i++) {
            const int pi = pad_idx(wbase + i);
            sP[wrp][pi] = e[i] + base_e;
            sQ[wrp][pi] = q[i] + base_q;
        }
        __syncwarp();
        #pragma unroll
        for (int i = 0; i < 8; i++) {
            const int w = wbase + i;
            const int m = min(dmax - 1, w);
            if (m < dmin) {
                res[i] = meanD;      // no valid disparity: uniform -> mean
            } else {
                const int hi = w - dmin;
                const int lo = w - m;
                const float ph = sP[wrp][pad_idx(hi)];
                const float qh = sQ[wrp][pad_idx(hi)];
                float pb = 0.0f, qb = 0.0f;
                if (lo > 0) {
                    const int bi = pad_idx(lo - 1);
                    pb = sP[wrp][bi];
                    qb = sQ[wrp][bi];
                }
                const float dP = ph - pb;
                const float dQ = qh - qb;
                const int   nValid = m - dmin + 1;
                const int   nInv   = D - nValid;
                const float sumValid_d = 0.5f * (float)(m + dmin) * (float)nValid;
                const float s0 = dP + (float)nInv;
                const float s1 = (float)w * dP - dQ + (sumAll_d - sumValid_d);
                res[i] = __fdividef(s1, s0);
            }
        }
    }

    // ---- right-channel stores
    float* outR = outL + (size_t)GC_C * GC_H * GC_W;
    *(float4*)(outR)     = make_float4(res[0], res[1], res[2], res[3]);
    *(float4*)(outR + 4) = make_float4(res[4], res[5], res[6], res[7]);
}

extern "C" void kernel_launch(void* const* d_in, const int* in_sizes, int n_in,
                              void* d_out, int out_size)
{
    // metadata order: feaL (unused — left channels are constant), feaR, min_disp, max_disp
    const float* feaR = (const float*)d_in[1];
    const int* pmin = (n_in > 2) ? (const int*)d_in[2] : nullptr;
    const int* pmax = (n_in > 3) ? (const int*)d_in[3] : nullptr;
    float* out = (float*)d_out;

    dim3 grid((GC_C * GC_H) / RPB);   // 1024 blocks, 4 rows each
    dim3 block(32 * RPB);
    gcnet_softargmax_kernel<<<grid, block>>>(feaR, pmin, pmax, out);
}